// round 12
// baseline (speedup 1.0000x reference)
#include <cuda_runtime.h>
#include <math_constants.h>

// ---------------------------------------------------------------------------
// EstimatorQNN, 2 qubits, 2 layers — two-kernel structure (R3 shape), fast
// setup (R12).
//
// Algebra: encoded state psi = (c0,s0)(x)(c1,s1); variational circuit = fixed
// 4x4 unitary U(weights); <Z0> = psi^T S psi, S = Re(U^H (Z(x)I) U).
// Double-angle collapse: result = 9 coefficients K over
// {1,cos(pi x0),sin(pi x0)} x {1,cos(pi x1),sin(pi x1)} -> 2 sincos + 8 FMA.
//
// Evidence-driven structure:
//  * R3's flat main kernel is the fastest streaming engine measured
//    (9.38 us, 3.58 TB/s): flat 4096x256, 4 samples/thread. Keep it EXACTLY;
//    add only __ldcs/__stcs streaming hints (zero-reuse data).
//  * All fusion attempts (R6/R9/R10/R11) degraded steady state more than the
//    setup they saved. So: separate build_K kernel, but with PARALLEL 3x
//    float4 weight prefetch (R7 fix) -> ~0.6 us instead of R3's ~2.5 us of
//    12 serialized dependent weight LDGs.
// ---------------------------------------------------------------------------

__device__ float d_K[9];  // {K1, KC1, KS1, KC0, KC0C1, KC0S1, KS0, KS0C1, KS0S1}

struct Cx { float re, im; };

__device__ __forceinline__ Cx cmul(Cx a, Cx b) {
    Cx r; r.re = a.re * b.re - a.im * b.im; r.im = a.re * b.im + a.im * b.re; return r;
}
__device__ __forceinline__ Cx cadd(Cx a, Cx b) { Cx r; r.re = a.re + b.re; r.im = a.im + b.im; return r; }

__device__ __forceinline__ void apply_gate(Cx s[4], Cx m00, Cx m01, Cx m10, Cx m11, int q) {
    if (q == 0) {
#pragma unroll
        for (int j = 0; j < 2; j++) {
            Cx a = s[j], b = s[j + 2];
            s[j]     = cadd(cmul(m00, a), cmul(m01, b));
            s[j + 2] = cadd(cmul(m10, a), cmul(m11, b));
        }
    } else {
#pragma unroll
        for (int j = 0; j < 4; j += 2) {
            Cx a = s[j], b = s[j + 1];
            s[j]     = cadd(cmul(m00, a), cmul(m01, b));
            s[j + 1] = cadd(cmul(m10, a), cmul(m11, b));
        }
    }
}

// Single-warp setup kernel. Weights prefetched as 3x float4 (one load
// latency); threads 0-3 simulate the 4 basis columns; shuffle-based exchange
// via shared; thread 0 folds S into the 9 double-angle coefficients.
__global__ void build_K_kernel(const float4* __restrict__ w4) {
    __shared__ Cx U[4][4];   // U[k][b]
    __shared__ float S[4][4];
    int t = threadIdx.x;

    float4 w0 = w4[0], w1 = w4[1], w2 = w4[2];   // parallel, all threads
    float wr[12] = {w0.x, w0.y, w0.z, w0.w,
                    w1.x, w1.y, w1.z, w1.w,
                    w2.x, w2.y, w2.z, w2.w};

    if (t < 4) {
        int b = t;
        Cx s[4];
#pragma unroll
        for (int k = 0; k < 4; k++) { s[k].re = (k == b) ? 1.0f : 0.0f; s[k].im = 0.0f; }
#pragma unroll
        for (int layer = 0; layer < 2; layer++) {
            int off = layer * 6;
#pragma unroll
            for (int q = 0; q < 2; q++) {
                float tx = wr[off + q * 3 + 0];
                float tz = wr[off + q * 3 + 1];
                float ty = wr[off + q * 3 + 2];
                float c, sn;
                c = __cosf(0.5f * tx); sn = __sinf(0.5f * tx);
                { Cx m00{c,0}, m01{0,-sn}, m10{0,-sn}, m11{c,0};
                  apply_gate(s, m00, m01, m10, m11, q); }
                c = __cosf(0.5f * tz); sn = __sinf(0.5f * tz);
                { Cx m00{c,-sn}, m01{0,0}, m10{0,0}, m11{c,sn};
                  apply_gate(s, m00, m01, m10, m11, q); }
                c = __cosf(0.5f * ty); sn = __sinf(0.5f * ty);
                { Cx m00{c,0}, m01{-sn,0}, m10{sn,0}, m11{c,0};
                  apply_gate(s, m00, m01, m10, m11, q); }
            }
            Cx tmp = s[2]; s[2] = s[3]; s[3] = tmp;  // CNOT(0->1): swap |10>,|11>
        }
#pragma unroll
        for (int k = 0; k < 4; k++) U[k][b] = s[k];
    }
    __syncwarp();
    if (t < 16) {
        int i = t >> 2, j = t & 3;
        float acc = 0.0f;
#pragma unroll
        for (int k = 0; k < 4; k++) {
            float zk = (k < 2) ? 1.0f : -1.0f;
            acc += zk * (U[k][i].re * U[k][j].re + U[k][i].im * U[k][j].im);
        }
        S[i][j] = acc;
    }
    __syncwarp();
    if (t == 0) {
        float c0 = S[0][0], c1 = S[1][1], c2 = S[2][2], c3 = S[3][3];
        float c4 = 2.0f * S[0][1], c5 = 2.0f * S[0][2], c6 = 2.0f * S[0][3];
        float c7 = 2.0f * S[1][2], c8 = 2.0f * S[1][3], c9 = 2.0f * S[2][3];
        d_K[0] = 0.25f * (c0 + c1 + c2 + c3);   // 1
        d_K[1] = 0.25f * (c0 - c1 + c2 - c3);   // C1
        d_K[2] = 0.25f * (c4 + c9);             // S1
        d_K[3] = 0.25f * (c0 + c1 - c2 - c3);   // C0
        d_K[4] = 0.25f * (c0 - c1 - c2 + c3);   // C0*C1
        d_K[5] = 0.25f * (c4 - c9);             // C0*S1
        d_K[6] = 0.25f * (c5 + c8);             // S0
        d_K[7] = 0.25f * (c5 - c8);             // S0*C1
        d_K[8] = 0.25f * (c6 + c7);             // S0*S1
    }
}

__device__ __forceinline__ float eval_one(float x0, float x1, const float k[9]) {
    float S0, C0, S1, C1;
    __sincosf(CUDART_PI_F * x0, &S0, &C0);
    __sincosf(CUDART_PI_F * x1, &S1, &C1);
    float t1 = fmaf(k[2], S1, fmaf(k[1], C1, k[0]));
    float t2 = fmaf(k[5], S1, fmaf(k[4], C1, k[3]));
    float t3 = fmaf(k[8], S1, fmaf(k[7], C1, k[6]));
    return fmaf(S0, t3, fmaf(C0, t2, t1));
}

// Flat main kernel, R3 shape: 4 samples/thread, 2x float4 in (streaming),
// 1x float4 out (streaming).
__global__ void __launch_bounds__(256, 8) qnn_main_kernel(
    const float4* __restrict__ in, float4* __restrict__ out, int n_quads) {
    int i = blockIdx.x * blockDim.x + threadIdx.x;
    float k[9];
#pragma unroll
    for (int j = 0; j < 9; j++) k[j] = d_K[j];
    if (i >= n_quads) return;
    float4 a = __ldcs(&in[2 * (size_t)i]);
    float4 b = __ldcs(&in[2 * (size_t)i + 1]);
    float4 r;
    r.x = eval_one(a.x, a.y, k);
    r.y = eval_one(a.z, a.w, k);
    r.z = eval_one(b.x, b.y, k);
    r.w = eval_one(b.z, b.w, k);
    __stcs(&out[i], r);
}

// Scalar tail for B % 4 != 0 (not hit for B = 4194304).
__global__ void qnn_tail_kernel(const float2* __restrict__ in,
                                float* __restrict__ out, int start, int B) {
    float k[9];
#pragma unroll
    for (int j = 0; j < 9; j++) k[j] = d_K[j];
    int i = start + blockIdx.x * blockDim.x + threadIdx.x;
    if (i >= B) return;
    float2 x = in[i];
    out[i] = eval_one(x.x, x.y, k);
}

extern "C" void kernel_launch(void* const* d_in, const int* in_sizes, int n_in,
                              void* d_out, int out_size) {
    const float* inputs  = (const float*)d_in[0];   // [B,2]
    const float* weights = (const float*)d_in[1];   // [12]

    build_K_kernel<<<1, 32>>>((const float4*)weights);

    int B = in_sizes[0] / 2;            // 4194304
    int n_quads = B / 4;                // 1048576
    if (n_quads > 0) {
        int threads = 256;
        int blocks = (n_quads + threads - 1) / threads;   // 4096
        qnn_main_kernel<<<blocks, threads>>>((const float4*)inputs,
                                             (float4*)d_out, n_quads);
    }
    int done = n_quads * 4;
    if (done < B) {
        int rem = B - done;
        qnn_tail_kernel<<<(rem + 127) / 128, 128>>>((const float2*)inputs,
                                                    (float*)d_out, done, B);
    }
}

// round 13
// speedup vs baseline: 1.0912x; 1.0912x over previous
#include <cuda_runtime.h>
#include <math_constants.h>

// ---------------------------------------------------------------------------
// EstimatorQNN, 2 qubits, 2 layers — two-kernel + PDL overlap (R13).
//
// Algebra: encoded state psi = (c0,s0)(x)(c1,s1); variational circuit = fixed
// 4x4 unitary U(weights); <Z0> = psi^T S psi, S = Re(U^H (Z(x)I) U).
// Double-angle collapse: result = 9 coefficients K over
// {1,cos(pi x0),sin(pi x0)} x {1,cos(pi x1),sin(pi x1)} -> 2 sincos + 8 FMA.
//
// R12 decomposition: main kernel 9.44 us (best streaming shape), but ~2.8 us
// of build_K + serialized launch latency. R13 hides that with programmatic
// dependent launch: build_K triggers launch_dependents at entry; the main
// kernel launches concurrently, issues its input loads, THEN
// griddepcontrol.wait-s for build_K's d_K writes. Steady state untouched.
// ---------------------------------------------------------------------------

__device__ float d_K[9];  // {K1, KC1, KS1, KC0, KC0C1, KC0S1, KS0, KS0C1, KS0S1}

struct Cx { float re, im; };

__device__ __forceinline__ Cx cmul(Cx a, Cx b) {
    Cx r; r.re = a.re * b.re - a.im * b.im; r.im = a.re * b.im + a.im * b.re; return r;
}
__device__ __forceinline__ Cx cadd(Cx a, Cx b) { Cx r; r.re = a.re + b.re; r.im = a.im + b.im; return r; }

__device__ __forceinline__ void apply_gate(Cx s[4], Cx m00, Cx m01, Cx m10, Cx m11, int q) {
    if (q == 0) {
#pragma unroll
        for (int j = 0; j < 2; j++) {
            Cx a = s[j], b = s[j + 2];
            s[j]     = cadd(cmul(m00, a), cmul(m01, b));
            s[j + 2] = cadd(cmul(m10, a), cmul(m11, b));
        }
    } else {
#pragma unroll
        for (int j = 0; j < 4; j += 2) {
            Cx a = s[j], b = s[j + 1];
            s[j]     = cadd(cmul(m00, a), cmul(m01, b));
            s[j + 1] = cadd(cmul(m10, a), cmul(m11, b));
        }
    }
}

// Single-warp setup kernel. Signals dependent launch immediately, then
// derives the 9 K coefficients (weights prefetched as 3x float4).
__global__ void build_K_kernel(const float4* __restrict__ w4) {
    // Let the dependent (main) grid start launching right away.
    asm volatile("griddepcontrol.launch_dependents;");

    __shared__ Cx U[4][4];   // U[k][b]
    __shared__ float S[4][4];
    int t = threadIdx.x;

    float4 w0 = w4[0], w1 = w4[1], w2 = w4[2];   // parallel, one load latency
    float wr[12] = {w0.x, w0.y, w0.z, w0.w,
                    w1.x, w1.y, w1.z, w1.w,
                    w2.x, w2.y, w2.z, w2.w};

    if (t < 4) {
        int b = t;
        Cx s[4];
#pragma unroll
        for (int k = 0; k < 4; k++) { s[k].re = (k == b) ? 1.0f : 0.0f; s[k].im = 0.0f; }
#pragma unroll
        for (int layer = 0; layer < 2; layer++) {
            int off = layer * 6;
#pragma unroll
            for (int q = 0; q < 2; q++) {
                float tx = wr[off + q * 3 + 0];
                float tz = wr[off + q * 3 + 1];
                float ty = wr[off + q * 3 + 2];
                float c, sn;
                c = __cosf(0.5f * tx); sn = __sinf(0.5f * tx);
                { Cx m00{c,0}, m01{0,-sn}, m10{0,-sn}, m11{c,0};
                  apply_gate(s, m00, m01, m10, m11, q); }
                c = __cosf(0.5f * tz); sn = __sinf(0.5f * tz);
                { Cx m00{c,-sn}, m01{0,0}, m10{0,0}, m11{c,sn};
                  apply_gate(s, m00, m01, m10, m11, q); }
                c = __cosf(0.5f * ty); sn = __sinf(0.5f * ty);
                { Cx m00{c,0}, m01{-sn,0}, m10{sn,0}, m11{c,0};
                  apply_gate(s, m00, m01, m10, m11, q); }
            }
            Cx tmp = s[2]; s[2] = s[3]; s[3] = tmp;  // CNOT(0->1): swap |10>,|11>
        }
#pragma unroll
        for (int k = 0; k < 4; k++) U[k][b] = s[k];
    }
    __syncwarp();
    if (t < 16) {
        int i = t >> 2, j = t & 3;
        float acc = 0.0f;
#pragma unroll
        for (int k = 0; k < 4; k++) {
            float zk = (k < 2) ? 1.0f : -1.0f;
            acc += zk * (U[k][i].re * U[k][j].re + U[k][i].im * U[k][j].im);
        }
        S[i][j] = acc;
    }
    __syncwarp();
    if (t == 0) {
        float c0 = S[0][0], c1 = S[1][1], c2 = S[2][2], c3 = S[3][3];
        float c4 = 2.0f * S[0][1], c5 = 2.0f * S[0][2], c6 = 2.0f * S[0][3];
        float c7 = 2.0f * S[1][2], c8 = 2.0f * S[1][3], c9 = 2.0f * S[2][3];
        d_K[0] = 0.25f * (c0 + c1 + c2 + c3);   // 1
        d_K[1] = 0.25f * (c0 - c1 + c2 - c3);   // C1
        d_K[2] = 0.25f * (c4 + c9);             // S1
        d_K[3] = 0.25f * (c0 + c1 - c2 - c3);   // C0
        d_K[4] = 0.25f * (c0 - c1 - c2 + c3);   // C0*C1
        d_K[5] = 0.25f * (c4 - c9);             // C0*S1
        d_K[6] = 0.25f * (c5 + c8);             // S0
        d_K[7] = 0.25f * (c5 - c8);             // S0*C1
        d_K[8] = 0.25f * (c6 + c7);             // S0*S1
    }
}

__device__ __forceinline__ float eval_one(float x0, float x1, const float k[9]) {
    float S0, C0, S1, C1;
    __sincosf(CUDART_PI_F * x0, &S0, &C0);
    __sincosf(CUDART_PI_F * x1, &S1, &C1);
    float t1 = fmaf(k[2], S1, fmaf(k[1], C1, k[0]));
    float t2 = fmaf(k[5], S1, fmaf(k[4], C1, k[3]));
    float t3 = fmaf(k[8], S1, fmaf(k[7], C1, k[6]));
    return fmaf(S0, t3, fmaf(C0, t2, t1));
}

// Flat main kernel, R3 shape: 4 samples/thread, 2x float4 in (streaming),
// 1x float4 out (streaming). PDL: loads issue BEFORE the griddepcontrol.wait,
// so build_K's execution + this kernel's launch latency hide under them.
__global__ void __launch_bounds__(256, 8) qnn_main_kernel(
    const float4* __restrict__ in, float4* __restrict__ out, int n_quads) {
    int i = blockIdx.x * blockDim.x + threadIdx.x;
    bool valid = (i < n_quads);

    float4 a, b;
    if (valid) {
        a = __ldcs(&in[2 * (size_t)i]);
        b = __ldcs(&in[2 * (size_t)i + 1]);
    }

    // Wait for build_K's d_K writes to be visible (one-shot global event;
    // satisfied immediately for all waves after the first).
    asm volatile("griddepcontrol.wait;" ::: "memory");

    float k[9];
#pragma unroll
    for (int j = 0; j < 9; j++) k[j] = d_K[j];

    if (!valid) return;

    float4 r;
    r.x = eval_one(a.x, a.y, k);
    r.y = eval_one(a.z, a.w, k);
    r.z = eval_one(b.x, b.y, k);
    r.w = eval_one(b.z, b.w, k);
    __stcs(&out[i], r);
}

// Scalar tail for B % 4 != 0 (not hit for B = 4194304). Ordinary stream
// ordering: runs after main, build_K long complete.
__global__ void qnn_tail_kernel(const float2* __restrict__ in,
                                float* __restrict__ out, int start, int B) {
    float k[9];
#pragma unroll
    for (int j = 0; j < 9; j++) k[j] = d_K[j];
    int i = start + blockIdx.x * blockDim.x + threadIdx.x;
    if (i >= B) return;
    float2 x = in[i];
    out[i] = eval_one(x.x, x.y, k);
}

extern "C" void kernel_launch(void* const* d_in, const int* in_sizes, int n_in,
                              void* d_out, int out_size) {
    const float* inputs  = (const float*)d_in[0];   // [B,2]
    const float* weights = (const float*)d_in[1];   // [12]

    build_K_kernel<<<1, 32>>>((const float4*)weights);

    int B = in_sizes[0] / 2;            // 4194304
    int n_quads = B / 4;                // 1048576
    if (n_quads > 0) {
        int threads = 256;
        int blocks = (n_quads + threads - 1) / threads;   // 4096

        cudaLaunchConfig_t cfg = {};
        cfg.gridDim = dim3((unsigned)blocks, 1, 1);
        cfg.blockDim = dim3((unsigned)threads, 1, 1);
        cfg.dynamicSmemBytes = 0;
        cfg.stream = 0;   // legacy default stream (same one <<<>>> uses)

        cudaLaunchAttribute attrs[1];
        attrs[0].id = cudaLaunchAttributeProgrammaticStreamSerialization;
        attrs[0].val.programmaticStreamSerializationAllowed = 1;
        cfg.attrs = attrs;
        cfg.numAttrs = 1;

        cudaLaunchKernelEx(&cfg, qnn_main_kernel,
                           (const float4*)inputs, (float4*)d_out, n_quads);
    }
    int done = n_quads * 4;
    if (done < B) {
        int rem = B - done;
        qnn_tail_kernel<<<(rem + 127) / 128, 128>>>((const float2*)inputs,
                                                    (float*)d_out, done, B);
    }
}